// round 10
// baseline (speedup 1.0000x reference)
#include <cuda_runtime.h>
#include <cuda_bf16.h>
#include <cstdint>

#define S   512
#define DH  128
#define NH  16

// scratch for precomputed hi / hj (B=2)
__device__ float g_hi[2 * S * DH];
__device__ float g_hj[2 * S * DH];

// ---------------------------------------------------------------------------
// helpers
// ---------------------------------------------------------------------------
__device__ __forceinline__ uint32_t smem_u32(const void* p) {
    uint32_t a;
    asm("{ .reg .u64 t; cvta.to.shared.u64 t, %1; cvt.u32.u64 %0, t; }"
        : "=r"(a) : "l"(p));
    return a;
}

__device__ __forceinline__ void ldsm4(uint32_t* r, uint32_t addr) {
    asm volatile("ldmatrix.sync.aligned.m8n8.x4.shared.b16 {%0,%1,%2,%3}, [%4];"
                 : "=r"(r[0]), "=r"(r[1]), "=r"(r[2]), "=r"(r[3]) : "r"(addr));
}

__device__ __forceinline__ void mma16816(float* c, const uint32_t* a,
                                         uint32_t b0, uint32_t b1) {
    asm volatile(
        "mma.sync.aligned.m16n8k16.row.col.f32.bf16.bf16.f32 "
        "{%0,%1,%2,%3}, {%4,%5,%6,%7}, {%8,%9}, {%0,%1,%2,%3};"
        : "+f"(c[0]), "+f"(c[1]), "+f"(c[2]), "+f"(c[3])
        : "r"(a[0]), "r"(a[1]), "r"(a[2]), "r"(a[3]), "r"(b0), "r"(b1));
}

__device__ __forceinline__ void bsplit(float v, unsigned short& h, unsigned short& l) {
    __nv_bfloat16 bh = __float2bfloat16_rn(v);
    float r = v - __bfloat162float(bh);
    h = __bfloat16_as_ushort(bh);
    l = __bfloat16_as_ushort(__float2bfloat16_rn(r));
}
__device__ __forceinline__ uint32_t pack2(float v0, float v1, uint32_t& lo) {
    unsigned short h0, l0, h1, l1;
    bsplit(v0, h0, l0); bsplit(v1, h1, l1);
    lo = (uint32_t)l0 | ((uint32_t)l1 << 16);
    return (uint32_t)h0 | ((uint32_t)h1 << 16);
}

// ---------------------------------------------------------------------------
// smem layout (bytes). bf16 matrices use row stride 136 elems = 272 B
// (272/4 = 68 ≡ 4 mod 32 -> ldmatrix conflict-free).
// ---------------------------------------------------------------------------
#define SA   136      // bf16 row stride (elems)
#define SAB  272      // bytes
#define SJF  129      // hj fp32 row stride
#define SPRT 17       // layer-3 partial buffer stride (floats)

#define HI_OFF   0        // 8  * 128 f32  (4096)   | also layer-3 partials (128*17*4 = 8704)
#define HJ_OFF   4096     // 16 * 129 f32  (8256)
#define B2_OFF   12416    // 128 f32
#define B3_OFF   12928    // 16 f32
#define TP_OFF   12992    // 16 f32
#define W2H_OFF  13056    // 128*136 bf16 (34816)
#define W2L_OFF  47872
#define W3H_OFF  82688    // 16*136 bf16 (4352)
#define W3L_OFF  87040
#define AH_OFF   91392    // 128*136 bf16 (A / h2 hi)
#define AL_OFF   126208
#define PART_OFF 0        // overlaps HI/HJ staging area (dead during layer-3)
#define SMEM_TOTAL 161024

// ---------------------------------------------------------------------------
// Kernel 1: hi = x @ W1[:128] + b1 ;  hj = x @ W1[128:]
// ---------------------------------------------------------------------------
__global__ void precompute_kernel(const float* __restrict__ x,
                                  const float* __restrict__ W1,
                                  const float* __restrict__ b1) {
    __shared__ float xs[DH];
    const int row = blockIdx.x;
    const int t   = threadIdx.x;
    xs[t] = x[row * DH + t];
    __syncthreads();
    float ai = b1[t];
    float aj = 0.f;
#pragma unroll 8
    for (int d = 0; d < DH; ++d) {
        const float xv = xs[d];
        ai = fmaf(xv, W1[d * DH + t], ai);
        aj = fmaf(xv, W1[(DH + d) * DH + t], aj);
    }
    g_hi[row * DH + t] = ai;
    g_hj[row * DH + t] = aj;
}

// ---------------------------------------------------------------------------
// Kernel 2: persistent mma.sync pairwise-MLP. 512 thr = 16 warps.
// Tile = 128 pairs (8 i x 16 j).
// Layer2: warp grid 4(M) x 4(N), warp tile M32 x N32.
// Layer3: 16 warps, K-split pairs (wid, wid+8) per m16-row-tile.
// ---------------------------------------------------------------------------
__global__ __launch_bounds__(512, 1)
void main_kernel(const float* __restrict__ W2, const float* __restrict__ b2,
                 const float* __restrict__ W3, const float* __restrict__ b3,
                 const float* __restrict__ temps, const uint32_t* __restrict__ mask,
                 float* __restrict__ out, int ntiles) {
    extern __shared__ __align__(1024) char smc[];
    const uint32_t smu = smem_u32(smc);
    const int tid = threadIdx.x;
    const int wid = tid >> 5;
    const int lid = tid & 31;

    // ---- one-time staging ----
    for (int idx = tid; idx < DH * DH; idx += 512) {       // W2[k][n] -> [n][k]
        const int k = idx >> 7, n = idx & 127;
        unsigned short h, l; bsplit(W2[idx], h, l);
        const uint32_t off = (uint32_t)(n * SAB + k * 2);
        *(unsigned short*)(smc + W2H_OFF + off) = h;
        *(unsigned short*)(smc + W2L_OFF + off) = l;
    }
    for (int idx = tid; idx < DH * NH; idx += 512) {       // W3[k][c] -> [c][k]
        const int k = idx >> 4, c = idx & 15;
        unsigned short h, l; bsplit(W3[idx], h, l);
        const uint32_t off = (uint32_t)(c * SAB + k * 2);
        *(unsigned short*)(smc + W3H_OFF + off) = h;
        *(unsigned short*)(smc + W3L_OFF + off) = l;
    }
    if (tid < DH) ((float*)(smc + B2_OFF))[tid] = b2[tid];
    if (tid < NH) {
        ((float*)(smc + B3_OFF))[tid] = b3[tid];
        ((float*)(smc + TP_OFF))[tid] = temps[tid];
    }

    const float* b2s = (const float*)(smc + B2_OFF);
    const float* b3s = (const float*)(smc + B3_OFF);
    const float* tps = (const float*)(smc + TP_OFF);
    float* part = (float*)(smc + PART_OFF);

    // ldmatrix lane address pattern
    const uint32_t lrow  = (uint32_t)(lid & 15);
    const uint32_t lcolb = (uint32_t)(((lid >> 4) << 3) << 1);

    // layer-2 warp tiling: 4x4
    const int wm = wid & 3;
    const int wn = wid >> 2;
    const int m_base = wm * 32;
    const int n_base = wn * 32;

    uint32_t aoffH[2], aoffL[2], boffH[2], boffL[2];
#pragma unroll
    for (int mt = 0; mt < 2; ++mt) {
        const uint32_t off = (uint32_t)(m_base + mt * 16 + lrow) * SAB + lcolb;
        aoffH[mt] = smu + AH_OFF + off;
        aoffL[mt] = smu + AL_OFF + off;
    }
#pragma unroll
    for (int np = 0; np < 2; ++np) {
        const uint32_t off = (uint32_t)(n_base + np * 16 + lrow) * SAB + lcolb;
        boffH[np] = smu + W2H_OFF + off;
        boffL[np] = smu + W2L_OFF + off;
    }

    // layer-3: warp pair (w, w+8) covers rows (w&7)*16, K halves
    const int mrow3  = (wid & 7) * 16;
    const int khalf3 = (wid >> 3) << 6;                    // 0 or 64
    const uint32_t a3off  = smu + AH_OFF + (uint32_t)(mrow3 + lrow) * SAB
                            + (uint32_t)khalf3 * 2 + lcolb;
    const uint32_t a3offL = a3off + (AL_OFF - AH_OFF);
    const uint32_t b3offH = smu + W3H_OFF + lrow * SAB + (uint32_t)khalf3 * 2 + lcolb;
    const uint32_t b3offL = b3offH + (W3L_OFF - W3H_OFF);

    const int qr = lid >> 2;           // 0..7
    const int qc = (lid & 3) << 1;     // 0,2,4,6

    for (int t = blockIdx.x; t < ntiles; t += gridDim.x) {
        const int b  = t >> 11;
        const int r  = t & 2047;
        const int i0 = (r >> 5) << 3;
        const int j0 = (r & 31) << 4;

        // ---- stage hi / hj ----
        {
            const float* src = g_hi + ((size_t)(b * S + i0)) * DH;
            for (int idx = tid; idx < 8 * DH; idx += 512)
                ((float*)(smc + HI_OFF))[idx] = src[idx];
            src = g_hj + ((size_t)(b * S + j0)) * DH;
            for (int idx = tid; idx < 16 * DH; idx += 512)
                ((float*)(smc + HJ_OFF))[(idx >> 7) * SJF + (idx & 127)] = src[idx];
        }
        __syncthreads();

        // ---- build A = relu(hi+hj) -> bf16 hi/lo ----
        {
            const int m  = tid >> 2;                  // 0..127
            const int k0 = (tid & 3) << 5;            // 0,32,64,96
            const float* hip = (const float*)(smc + HI_OFF) + (m >> 4) * DH + k0;
            const float* hjp = (const float*)(smc + HJ_OFF) + (m & 15) * SJF + k0;
            const uint32_t wbase = (uint32_t)m * SAB + (uint32_t)k0 * 2;
#pragma unroll
            for (int kk = 0; kk < 32; kk += 2) {
                const float v0 = fmaxf(hip[kk]     + hjp[kk],     0.f);
                const float v1 = fmaxf(hip[kk + 1] + hjp[kk + 1], 0.f);
                uint32_t lo;
                const uint32_t hi = pack2(v0, v1, lo);
                *(uint32_t*)(smc + AH_OFF + wbase + kk * 2) = hi;
                *(uint32_t*)(smc + AL_OFF + wbase + kk * 2) = lo;
            }
        }
        __syncthreads();

        // ---- layer-2 GEMM: acc = Ah*Bh + Ah*Bl + Al*Bh ----
        float acc[2][4][4];
#pragma unroll
        for (int mt = 0; mt < 2; ++mt)
#pragma unroll
            for (int nt = 0; nt < 4; ++nt)
#pragma unroll
                for (int e = 0; e < 4; ++e) acc[mt][nt][e] = 0.f;

#pragma unroll
        for (int k0 = 0; k0 < 128; k0 += 16) {
            const uint32_t kb = (uint32_t)k0 * 2;
            uint32_t aH[2][4], aL[2][4], bH[2][4], bL[2][4];
#pragma unroll
            for (int mt = 0; mt < 2; ++mt) {
                ldsm4(aH[mt], aoffH[mt] + kb);
                ldsm4(aL[mt], aoffL[mt] + kb);
            }
#pragma unroll
            for (int np = 0; np < 2; ++np) {
                ldsm4(bH[np], boffH[np] + kb);
                ldsm4(bL[np], boffL[np] + kb);
            }
#pragma unroll
            for (int mt = 0; mt < 2; ++mt)
#pragma unroll
                for (int nt = 0; nt < 4; ++nt) {
                    const int np = nt >> 1, sc = nt & 1;
                    mma16816(acc[mt][nt], aH[mt], bH[np][sc], bH[np][2 + sc]);
                    mma16816(acc[mt][nt], aH[mt], bL[np][sc], bL[np][2 + sc]);
                    mma16816(acc[mt][nt], aL[mt], bH[np][sc], bH[np][2 + sc]);
                }
        }
        __syncthreads();   // all Ah/Al reads done

        // ---- epilogue 1: h2 = relu(acc + b2) -> bf16 hi/lo back into A ----
#pragma unroll
        for (int mt = 0; mt < 2; ++mt)
#pragma unroll
            for (int nt = 0; nt < 4; ++nt) {
                const int n0  = n_base + nt * 8 + qc;
                const float ba = b2s[n0], bb = b2s[n0 + 1];
                const int r0 = m_base + mt * 16 + qr;
                uint32_t lo0, lo1;
                const uint32_t hi0 = pack2(fmaxf(acc[mt][nt][0] + ba, 0.f),
                                           fmaxf(acc[mt][nt][1] + bb, 0.f), lo0);
                const uint32_t hi1 = pack2(fmaxf(acc[mt][nt][2] + ba, 0.f),
                                           fmaxf(acc[mt][nt][3] + bb, 0.f), lo1);
                const uint32_t w0 = (uint32_t)r0 * SAB + (uint32_t)n0 * 2;
                *(uint32_t*)(smc + AH_OFF + w0) = hi0;
                *(uint32_t*)(smc + AL_OFF + w0) = lo0;
                const uint32_t w1 = w0 + 8u * SAB;
                *(uint32_t*)(smc + AH_OFF + w1) = hi1;
                *(uint32_t*)(smc + AL_OFF + w1) = lo1;
            }
        __syncthreads();

        // ---- layer-3 GEMM (K-split): comp += h2h*W3h + h2h*W3l + h2l*W3h ----
        float acc2[2][4];
#pragma unroll
        for (int nt = 0; nt < 2; ++nt)
#pragma unroll
            for (int e = 0; e < 4; ++e) acc2[nt][e] = 0.f;

#pragma unroll
        for (int kk = 0; kk < 64; kk += 16) {
            const uint32_t kb = (uint32_t)kk * 2;
            uint32_t ah[4], al[4], bh[4], bl[4];
            ldsm4(ah, a3off + kb);
            ldsm4(al, a3offL + kb);
            ldsm4(bh, b3offH + kb);
            ldsm4(bl, b3offL + kb);
#pragma unroll
            for (int nt = 0; nt < 2; ++nt) {
                mma16816(acc2[nt], ah, bh[nt], bh[2 + nt]);
                mma16816(acc2[nt], ah, bl[nt], bl[2 + nt]);
                mma16816(acc2[nt], al, bh[nt], bh[2 + nt]);
            }
        }

        // upper-K warps publish partials (HI/HJ staging area is dead here)
        if (wid >= 8) {
#pragma unroll
            for (int e = 0; e < 2; ++e) {
                const int m = mrow3 + qr + e * 8;
#pragma unroll
                for (int nt = 0; nt < 2; ++nt) {
                    const int c0 = nt * 8 + qc;
                    part[m * SPRT + c0]     = acc2[nt][e * 2 + 0];
                    part[m * SPRT + c0 + 1] = acc2[nt][e * 2 + 1];
                }
            }
        }
        __syncthreads();

        // ---- epilogue 2: combine halves, scale, mask, store ----
        if (wid < 8) {
            const float ninf = __int_as_float(0xff800000);
            const size_t bb = (size_t)b * NH * S * S;
#pragma unroll
            for (int e = 0; e < 2; ++e) {
                const int m = mrow3 + qr + e * 8;
                const int i = i0 + (m >> 4);
                const int j = j0 + (m & 15);
                const bool mk = mask[((size_t)b * S + i) * S + j] != 0u;
                const size_t obase = bb + (size_t)i * S + j;
#pragma unroll
                for (int nt = 0; nt < 2; ++nt) {
                    const int c0 = nt * 8 + qc;
                    const float s0 = acc2[nt][e * 2 + 0] + part[m * SPRT + c0];
                    const float s1 = acc2[nt][e * 2 + 1] + part[m * SPRT + c0 + 1];
                    const float v0 = (s0 + b3s[c0])     * tps[c0];
                    const float v1 = (s1 + b3s[c0 + 1]) * tps[c0 + 1];
                    out[obase + (size_t)c0 * S * S]       = mk ? v0 : ninf;
                    out[obase + (size_t)(c0 + 1) * S * S] = mk ? v1 : ninf;
                }
            }
        }
        __syncthreads();   // protect partials from next tile's stage writes
    }
}

// ---------------------------------------------------------------------------
extern "C" void kernel_launch(void* const* d_in, const int* in_sizes, int n_in,
                              void* d_out, int out_size) {
    const float*    x     = (const float*)d_in[0];
    const uint32_t* mask  = (const uint32_t*)d_in[1];
    const float*    W1    = (const float*)d_in[2];
    const float*    b1    = (const float*)d_in[3];
    const float*    W2    = (const float*)d_in[4];
    const float*    b2    = (const float*)d_in[5];
    const float*    W3    = (const float*)d_in[6];
    const float*    b3    = (const float*)d_in[7];
    const float*    temps = (const float*)d_in[8];

    const int B = in_sizes[0] / (S * DH);   // = 2
    const int ntiles = B * 2048;            // 128-pair tiles

    cudaFuncSetAttribute(main_kernel, cudaFuncAttributeMaxDynamicSharedMemorySize,
                         SMEM_TOTAL);

    precompute_kernel<<<B * S, DH>>>(x, W1, b1);
    main_kernel<<<152, 512, SMEM_TOTAL>>>(W2, b2, W3, b3, temps, mask,
                                          (float*)d_out, ntiles);
}